// round 17
// baseline (speedup 1.0000x reference)
#include <cuda_runtime.h>

#define NN 4
#define BPTS 8192
#define CIN 32
#define DOUT 32
#define ANB 32
#define NBAS 36
#define TOTAL 32768
#define PPI 16              // points per pipeline iteration
#define THREADS 512         // 8 producer warps + 8 consumer warps
#define NITER (TOTAL/PPI)   // 2048
#define KK 1152
#define SP 1156             // MpT row stride: == 4 mod 32, even
#define BSW 1296            // per-producer-warp basis buffer
#define MPTSZ (PPI*SP)      // one MpT buffer (18496 floats)

typedef unsigned long long u64;
typedef unsigned int u32;

__device__ float g_inputT[NN*BPTS*CIN];       // (n,b,c), tf32-rounded
__device__ float g_wfrag[4*144*32*2];          // B-frags [dtile][kstep][lane][2], kk' = c*36+sr

// ---------------- helpers ----------------
__device__ __forceinline__ float tf32r(float x){
    float y; asm("cvt.rna.tf32.f32 %0,%1;" : "=f"(y) : "f"(x)); return y;
}
__device__ __forceinline__ void mma_tf32(float& d0, float& d1, float& d2, float& d3,
                                         u32 a0, u32 a1, u32 a2, u32 a3, u32 b0, u32 b1){
    asm volatile(
        "mma.sync.aligned.m16n8k8.row.col.f32.tf32.tf32.f32 "
        "{%0,%1,%2,%3}, {%4,%5,%6,%7}, {%8,%9}, {%0,%1,%2,%3};"
        : "+f"(d0), "+f"(d1), "+f"(d2), "+f"(d3)
        : "r"(a0), "r"(a1), "r"(a2), "r"(a3), "r"(b0), "r"(b1));
}
// named barriers: FULL = 1+par, EMPTY = 3+par (count 512); consumer-internal = 5 (count 256)
__device__ __forceinline__ void bar_sync_cnt(int id, int cnt){
    asm volatile("bar.sync %0, %1;" :: "r"(id), "r"(cnt) : "memory");
}
__device__ __forceinline__ void bar_arrive_cnt(int id, int cnt){
    asm volatile("bar.arrive %0, %1;" :: "r"(id), "r"(cnt) : "memory");
}

// ---------------- fused prep ----------------
__global__ void prep_all(const float* __restrict__ in, const float* __restrict__ W){
    const int bx = blockIdx.x;
    const int tid = threadIdx.x;           // 256
    if (bx < 1024){
        __shared__ float t[32][33];
        const int n  = bx >> 8;
        const int b0 = (bx & 255) * 32;
        const int tx = tid & 31, ty = tid >> 5;
        #pragma unroll
        for (int i = ty; i < 32; i += 8)
            t[i][tx] = in[(n*CIN + i)*BPTS + b0 + tx];
        __syncthreads();
        #pragma unroll
        for (int i = ty; i < 32; i += 8)
            g_inputT[(n*BPTS + b0 + i)*CIN + tx] = tf32r(t[tx][i]);
    } else {
        int t = (bx - 1024)*256 + tid;     // 36864 entries
        if (t < 4*144*32*2){
            int reg  = t & 1;
            int lane = (t >> 1) & 31;
            int rest = t >> 6;
            int kstep = rest % 144;
            int dtile = rest / 144;
            int g  = lane >> 2;
            int tt = lane & 3;
            int kkp = kstep*8 + tt + reg*4;   // kk' = c*36 + sr
            int c  = kkp / 36;
            int sr = kkp % 36;
            int r = sr & 3, s = sr >> 2;
            int d = dtile*8 + g;
            g_wfrag[t] = tf32r(W[(d*CIN + c)*NBAS + r*9 + s]);
        }
    }
}

// ---------------- main: warp-specialized pipeline ----------------
// smem floats: Bs 8*1296=10368 | MpT[2] 2*18496=36992 | redd 8w*32l*17=4352
// total 51712 f = 206848 B, 1 CTA/SM.
#define SM_BS   0
#define SM_MPT  10368
#define SM_RED  (10368 + 2*MPTSZ)
#define SM_FLOATS (SM_RED + 8*32*17)

__global__ void __launch_bounds__(THREADS, 1)
se3_main(const float* __restrict__ coords,
         const float* __restrict__ rmask,
         const int*   __restrict__ nbrs,
         float*       __restrict__ out)
{
    extern __shared__ float smem[];
    float* BsAll = smem + SM_BS;             // [pw][sr*36 + a]
    float* MpT0  = smem + SM_MPT;            // [buf][p*SP + kk']
    float* redd  = smem + SM_RED;            // [(cw*32+lane)*17 + ...]

    const int tid  = threadIdx.x;
    const int w    = tid >> 5;               // 0..15
    const int lane = tid & 31;
    const int g    = lane >> 2;
    const int tt   = lane & 3;

    const int nloc = (NITER - (int)blockIdx.x + (int)gridDim.x - 1) / (int)gridDim.x;

    if (w < 8){
        // =========================== PRODUCERS (warps 0..7) ===========================
        float* BsW = BsAll + w*BSW;
        for (int it = 0; it < nloc; it++){
            const int par = it & 1;
            if (it >= 2) bar_sync_cnt(3 + par, 512);          // wait EMPTY
            float* MpT = MpT0 + par*MPTSZ;

            const int grp = (int)blockIdx.x + it*(int)gridDim.x;
            const int flatbase = grp*PPI;
            const int n = flatbase >> 13;
            const float* fbase = g_inputT + (((long)n << 13) * CIN);

            #pragma unroll 1
            for (int sub = 0; sub < 2; sub++){
                const int p = w*2 + sub;
                const int flat = flatbase + p;

                // neighbor + batched feature prefetch
                const int nb_idx = flat*ANB + lane;
                const int jn  = nbrs[nb_idx];
                const float msk = rmask[nb_idx];

                float fv[4][8];
                #pragma unroll
                for (int ks = 0; ks < 4; ks++){
                    int jA = __shfl_sync(0xffffffffu, jn, ks*8 + tt);
                    int jB = __shfl_sync(0xffffffffu, jn, ks*8 + tt + 4);
                    const float* rowA = fbase + (long)jA*CIN;
                    const float* rowB = fbase + (long)jB*CIN;
                    fv[ks][0] = __ldg(rowA + g);
                    fv[ks][1] = __ldg(rowA + g + 8);
                    fv[ks][2] = __ldg(rowA + g + 16);
                    fv[ks][3] = __ldg(rowA + g + 24);
                    fv[ks][4] = __ldg(rowB + g);
                    fv[ks][5] = __ldg(rowB + g + 8);
                    fv[ks][6] = __ldg(rowB + g + 16);
                    fv[ks][7] = __ldg(rowB + g + 24);
                }

                // geometry + basis
                const float* cc = coords + (long)flat*3;
                const float c0x = cc[0], c0y = cc[1], c0z = cc[2];
                const float* cj = coords + ((long)(n*BPTS + jn))*3;
                const float dx = cj[0]-c0x, dy = cj[1]-c0y, dz = cj[2]-c0z;
                const float r  = sqrtf(dx*dx + dy*dy + dz*dz);
                const float inv = __fdividef(1.0f, r + 1e-8f);
                const float ux = dx*inv, uy = dy*inv, uz = dz*inv;
                float yv[9];
                yv[0] = 0.28209479f;
                yv[1] = 0.48860251f*ux; yv[2] = 0.48860251f*uy; yv[3] = 0.48860251f*uz;
                yv[4] = 1.09254843f*ux*uy; yv[5] = 1.09254843f*uy*uz;
                yv[6] = 0.31539157f*(3.0f*uz*uz - 1.0f);
                yv[7] = 1.09254843f*ux*uz;
                yv[8] = 0.54627421f*(ux*ux - uy*uy);
                float rb[4];
                {
                    float t0 = (r - 0.5f)*2.0f, t1 = (r - 1.0f)*2.0f;
                    float t2 = (r - 1.5f)*2.0f, t3 = (r - 2.0f)*2.0f;
                    rb[0] = msk*__expf(-t0*t0); rb[1] = msk*__expf(-t1*t1);
                    rb[2] = msk*__expf(-t2*t2); rb[3] = msk*__expf(-t3*t3);
                }
                #pragma unroll
                for (int s = 0; s < 9; s++){
                    #pragma unroll
                    for (int rr = 0; rr < 4; rr++)
                        BsW[(s*4 + rr)*36 + lane] = tf32r(rb[rr]*yv[s]);
                }
                __syncwarp();

                // 40 MMAs: M = feat^T * basis
                float acc[2][5][4];
                #pragma unroll
                for (int mt = 0; mt < 2; mt++)
                    #pragma unroll
                    for (int nt = 0; nt < 5; nt++)
                        #pragma unroll
                        for (int q = 0; q < 4; q++) acc[mt][nt][q] = 0.f;

                #pragma unroll
                for (int ks = 0; ks < 4; ks++){
                    u32 bbf[5][2];
                    #pragma unroll
                    for (int nt = 0; nt < 5; nt++){
                        const float* bp = BsW + (nt*8 + g)*36 + ks*8 + tt;
                        bbf[nt][0] = __float_as_uint(bp[0]);
                        bbf[nt][1] = __float_as_uint(bp[4]);
                    }
                    #pragma unroll
                    for (int mt = 0; mt < 2; mt++){
                        u32 a0 = __float_as_uint(fv[ks][mt*2 + 0]);
                        u32 a1 = __float_as_uint(fv[ks][mt*2 + 1]);
                        u32 a2 = __float_as_uint(fv[ks][mt*2 + 4]);
                        u32 a3 = __float_as_uint(fv[ks][mt*2 + 5]);
                        #pragma unroll
                        for (int nt = 0; nt < 5; nt++)
                            mma_tf32(acc[mt][nt][0], acc[mt][nt][1], acc[mt][nt][2], acc[mt][nt][3],
                                     a0, a1, a2, a3, bbf[nt][0], bbf[nt][1]);
                    }
                }
                // D -> MpT[p][c*36+sr]
                {
                    float* mbase = MpT + p*SP;
                    #pragma unroll
                    for (int mt = 0; mt < 2; mt++){
                        const int c0 = mt*16 + g;
                        #pragma unroll
                        for (int nt = 0; nt < 5; nt++){
                            const int sr0 = nt*8 + 2*tt;
                            if (sr0 < 36){
                                *(float2*)(mbase + c0*36 + sr0) =
                                    make_float2(tf32r(acc[mt][nt][0]), tf32r(acc[mt][nt][1]));
                                *(float2*)(mbase + (c0+8)*36 + sr0) =
                                    make_float2(tf32r(acc[mt][nt][2]), tf32r(acc[mt][nt][3]));
                            }
                        }
                    }
                }
                __syncwarp();
            }
            bar_arrive_cnt(1 + par, 512);                     // signal FULL
        }
    } else {
        // =========================== CONSUMERS (warps 8..15) ===========================
        const int cw   = w - 8;               // 0..7 = kq
        const int ctid = tid - 256;            // 0..255
        for (int j = 0; j < nloc; j++){
            const int par = j & 1;
            bar_sync_cnt(1 + par, 512);                       // wait FULL
            const float* MpT = MpT0 + par*MPTSZ;

            const int grp = (int)blockIdx.x + j*(int)gridDim.x;
            const int flatbase = grp*PPI;
            const int n   = flatbase >> 13;
            const int bb0 = flatbase & (BPTS-1);

            // Phase B: warp = kq; m16 x n32 via 4 MMAs per step
            {
                const int kq = cw;
                const float* arow = MpT + g*SP + kq*144 + tt;
                const uint2* wf = ((const uint2*)g_wfrag) + (kq*18)*32 + lane;

                float accB[4][4];
                #pragma unroll
                for (int nt = 0; nt < 4; nt++)
                    #pragma unroll
                    for (int q = 0; q < 4; q++) accB[nt][q] = 0.f;

                #pragma unroll
                for (int st = 0; st < 18; st++){
                    u32 a0 = __float_as_uint(arow[st*8]);
                    u32 a1 = __float_as_uint(arow[st*8 + 8*SP]);
                    u32 a2 = __float_as_uint(arow[st*8 + 4]);
                    u32 a3 = __float_as_uint(arow[st*8 + 8*SP + 4]);
                    #pragma unroll
                    for (int nt = 0; nt < 4; nt++){
                        uint2 wv = __ldg(wf + nt*144*32 + st*32);
                        mma_tf32(accB[nt][0], accB[nt][1], accB[nt][2], accB[nt][3],
                                 a0, a1, a2, a3, wv.x, wv.y);
                    }
                }
                float* rs = redd + (cw*32 + lane)*17;
                #pragma unroll
                for (int nt = 0; nt < 4; nt++)
                    #pragma unroll
                    for (int q = 0; q < 4; q++)
                        rs[nt*4 + q] = accB[nt][q];
            }
            bar_sync_cnt(5, 256);                              // redd visible to all consumers

            // reduce 8 k-slices + store
            #pragma unroll
            for (int half = 0; half < 2; half++){
                const int p = ctid & 15;
                const int d = (ctid >> 4) + half*16;
                const int g2  = p & 7;
                const int hi  = p >> 3;
                const int nt  = d >> 3;
                const int tq  = (d & 7) >> 1;
                const int q   = hi*2 + (d & 1);
                const int L   = g2*4 + tq;
                float v = 0.f;
                #pragma unroll
                for (int kq = 0; kq < 8; kq++)
                    v += redd[(kq*32 + L)*17 + nt*4 + q];
                out[((long)(n*DOUT + d))*BPTS + bb0 + p] = v;
            }
            bar_sync_cnt(5, 256);                              // reduce reads done before next redd writes
            bar_arrive_cnt(3 + par, 512);                      // signal EMPTY
        }
    }
}

// ---------------- launch ----------------
extern "C" void kernel_launch(void* const* d_in, const int* in_sizes, int n_in,
                              void* d_out, int out_size)
{
    const float* input  = (const float*)d_in[0];
    const float* coords = (const float*)d_in[1];
    const float* rmask  = (const float*)d_in[2];
    const float* W      = (const float*)d_in[3];
    const int*   nbrs   = (const int*)d_in[4];
    float* out = (float*)d_out;

    (void)in_sizes; (void)n_in; (void)out_size;

    prep_all<<<1168, 256>>>(input, W);

    int dev = 0; cudaGetDevice(&dev);
    int smcount = 148;
    cudaDeviceGetAttribute(&smcount, cudaDevAttrMultiProcessorCount, dev);

    size_t shmem = (size_t)SM_FLOATS * sizeof(float);   // 206848 B
    cudaFuncSetAttribute(se3_main, cudaFuncAttributeMaxDynamicSharedMemorySize, (int)shmem);
    se3_main<<<smcount, THREADS, shmem>>>(coords, rmask, nbrs, out);
}